// round 9
// baseline (speedup 1.0000x reference)
#include <cuda_runtime.h>
#include <cstdint>
#include <cstddef>

typedef unsigned long long u64;
typedef unsigned int u32;

#define B_SZ 64
#define T_SZ 2048
#define H_SZ 256
#define G4   1024   // 4*H

// 512MB scratch for xg = x @ W_i + bias, layout [m][gate*256+u]
__device__ float g_xg[(size_t)B_SZ * T_SZ * G4];

// ---------------- f32x2 helpers ----------------
__device__ __forceinline__ u64 pk2(float lo, float hi) {
    u64 r; asm("mov.b64 %0, {%1, %2};" : "=l"(r) : "f"(lo), "f"(hi)); return r;
}
__device__ __forceinline__ u64 dup2(float a) {
    u64 r; asm("mov.b64 %0, {%1, %1};" : "=l"(r) : "f"(a)); return r;
}
__device__ __forceinline__ u64 fma2(u64 a, u64 b, u64 c) {
    u64 d; asm("fma.rn.f32x2 %0, %1, %2, %3;" : "=l"(d) : "l"(a), "l"(b), "l"(c)); return d;
}
__device__ __forceinline__ u64 add2(u64 a, u64 b) {
    u64 d; asm("add.rn.f32x2 %0, %1, %2;" : "=l"(d) : "l"(a), "l"(b)); return d;
}
__device__ __forceinline__ void unpk(u64 v, float& lo, float& hi) {
    asm("mov.b64 {%0, %1}, %2;" : "=f"(lo), "=f"(hi) : "l"(v));
}

// ---------------- cluster / mbarrier helpers ----------------
__device__ __forceinline__ u32 smem_u32(const void* p) {
    u32 a;
    asm("{ .reg .u64 t; cvta.to.shared.u64 t, %1; cvt.u32.u64 %0, t; }" : "=r"(a) : "l"(p));
    return a;
}
__device__ __forceinline__ u32 mapa_sh(u32 a, u32 rk) {
    u32 r; asm("mapa.shared::cluster.u32 %0, %1, %2;" : "=r"(r) : "r"(a), "r"(rk)); return r;
}
__device__ __forceinline__ void cluster_sync_() {
    asm volatile("barrier.cluster.arrive.aligned;" ::: "memory");
    asm volatile("barrier.cluster.wait.aligned;" ::: "memory");
}
__device__ __forceinline__ void mbar_init(u32 a, u32 cnt) {
    asm volatile("mbarrier.init.shared.b64 [%0], %1;" :: "r"(a), "r"(cnt) : "memory");
}
__device__ __forceinline__ void mbar_expect(u32 a, u32 bytes) {
    asm volatile("mbarrier.arrive.expect_tx.shared.b64 _, [%0], %1;" :: "r"(a), "r"(bytes) : "memory");
}
__device__ __forceinline__ void mbar_wait(u32 a, u32 ph) {
    asm volatile(
        "{\n\t.reg .pred P;\n\t"
        "MW%=:\n\t"
        "mbarrier.try_wait.parity.acquire.cta.shared::cta.b64 P, [%0], %1, 0x989680;\n\t"
        "@!P bra MW%=;\n\t}"
        :: "r"(a), "r"(ph) : "memory");
}
__device__ __forceinline__ void st_async_b64(u32 dst, u64 v, u32 mb) {
    asm volatile(
        "st.async.shared::cluster.mbarrier::complete_tx::bytes.b64 [%0], %1, [%2];"
        :: "r"(dst), "l"(v), "r"(mb) : "memory");
}

// ---------------- activations (exact, MUFU-based) ----------------
__device__ __forceinline__ float sigm(float x) {
    return __fdividef(1.0f, 1.0f + __expf(-x));
}
__device__ __forceinline__ float tanh_(float x) {
    return 1.0f - __fdividef(2.0f, __expf(2.0f * x) + 1.0f);
}

// =====================================================================
// Phase 1: g_xg[m][1024] = x[m][256] @ W_i[256][1024] + bias
// 128x128 tile, 256 threads, 8x8 microtile, k-chunk 16,
// double-buffered smem with register prefetch (1 sync / iter).
// =====================================================================
__global__ __launch_bounds__(256, 2) void xw_gemm(
    const float* __restrict__ A,      // x    [131072, 256]
    const float* __restrict__ W,      // W_i  [256, 1024]
    const float* __restrict__ bias)   // [1024]
{
    __shared__ float As[2][16][132];
    __shared__ float Bs[2][16][132];

    const int tid = threadIdx.x;
    const int tx = tid & 15;
    const int ty = tid >> 4;
    const int mBase = blockIdx.y * 128;
    const int nBase = blockIdx.x * 128;

    const int arow0 = tid >> 2,         akq0 = tid & 3;
    const int arow1 = (tid + 256) >> 2, akq1 = (tid + 256) & 3;
    const int bk0   = tid >> 5,         bnq0 = tid & 31;
    const int bk1   = (tid + 256) >> 5, bnq1 = (tid + 256) & 31;

    u64 acc[8][4];
    {
        const float* bp = bias + nBase + tx * 8;
        u64 b0 = pk2(bp[0], bp[1]);
        u64 b1 = pk2(bp[2], bp[3]);
        u64 b2 = pk2(bp[4], bp[5]);
        u64 b3 = pk2(bp[6], bp[7]);
#pragma unroll
        for (int i = 0; i < 8; i++) { acc[i][0] = b0; acc[i][1] = b1; acc[i][2] = b2; acc[i][3] = b3; }
    }

    float4 a_r0, a_r1, b_r0, b_r1;
    a_r0 = *(const float4*)(A + (size_t)(mBase + arow0) * 256 + akq0 * 4);
    a_r1 = *(const float4*)(A + (size_t)(mBase + arow1) * 256 + akq1 * 4);
    b_r0 = *(const float4*)(W + (size_t)bk0 * 1024 + nBase + bnq0 * 4);
    b_r1 = *(const float4*)(W + (size_t)bk1 * 1024 + nBase + bnq1 * 4);
    As[0][akq0 * 4 + 0][arow0] = a_r0.x; As[0][akq0 * 4 + 1][arow0] = a_r0.y;
    As[0][akq0 * 4 + 2][arow0] = a_r0.z; As[0][akq0 * 4 + 3][arow0] = a_r0.w;
    As[0][akq1 * 4 + 0][arow1] = a_r1.x; As[0][akq1 * 4 + 1][arow1] = a_r1.y;
    As[0][akq1 * 4 + 2][arow1] = a_r1.z; As[0][akq1 * 4 + 3][arow1] = a_r1.w;
    *(float4*)&Bs[0][bk0][bnq0 * 4] = b_r0;
    *(float4*)&Bs[0][bk1][bnq1 * 4] = b_r1;
    __syncthreads();

    int p = 0;
#pragma unroll 1
    for (int kc = 0; kc < 16; kc++) {
        if (kc < 15) {
            const int kb = (kc + 1) * 16;
            a_r0 = *(const float4*)(A + (size_t)(mBase + arow0) * 256 + kb + akq0 * 4);
            a_r1 = *(const float4*)(A + (size_t)(mBase + arow1) * 256 + kb + akq1 * 4);
            b_r0 = *(const float4*)(W + (size_t)(kb + bk0) * 1024 + nBase + bnq0 * 4);
            b_r1 = *(const float4*)(W + (size_t)(kb + bk1) * 1024 + nBase + bnq1 * 4);
        }
#pragma unroll
        for (int k = 0; k < 16; k++) {
            float4 a0 = *(float4*)&As[p][k][ty * 8];
            float4 a1 = *(float4*)&As[p][k][ty * 8 + 4];
            float4 b0 = *(float4*)&Bs[p][k][tx * 8];
            float4 b1 = *(float4*)&Bs[p][k][tx * 8 + 4];
            u64 bb0 = pk2(b0.x, b0.y), bb1 = pk2(b0.z, b0.w);
            u64 bb2 = pk2(b1.x, b1.y), bb3 = pk2(b1.z, b1.w);
            float aa[8] = {a0.x, a0.y, a0.z, a0.w, a1.x, a1.y, a1.z, a1.w};
#pragma unroll
            for (int i = 0; i < 8; i++) {
                u64 ad = dup2(aa[i]);
                acc[i][0] = fma2(ad, bb0, acc[i][0]);
                acc[i][1] = fma2(ad, bb1, acc[i][1]);
                acc[i][2] = fma2(ad, bb2, acc[i][2]);
                acc[i][3] = fma2(ad, bb3, acc[i][3]);
            }
        }
        if (kc < 15) {
            const int pn = p ^ 1;
            As[pn][akq0 * 4 + 0][arow0] = a_r0.x; As[pn][akq0 * 4 + 1][arow0] = a_r0.y;
            As[pn][akq0 * 4 + 2][arow0] = a_r0.z; As[pn][akq0 * 4 + 3][arow0] = a_r0.w;
            As[pn][akq1 * 4 + 0][arow1] = a_r1.x; As[pn][akq1 * 4 + 1][arow1] = a_r1.y;
            As[pn][akq1 * 4 + 2][arow1] = a_r1.z; As[pn][akq1 * 4 + 3][arow1] = a_r1.w;
            *(float4*)&Bs[pn][bk0][bnq0 * 4] = b_r0;
            *(float4*)&Bs[pn][bk1][bnq1 * 4] = b_r1;
            __syncthreads();
            p = pn;
        }
    }

#pragma unroll
    for (int i = 0; i < 8; i++) {
        float o[8];
        unpk(acc[i][0], o[0], o[1]); unpk(acc[i][1], o[2], o[3]);
        unpk(acc[i][2], o[4], o[5]); unpk(acc[i][3], o[6], o[7]);
        float* cp = g_xg + (size_t)(mBase + ty * 8 + i) * 1024 + nBase + tx * 8;
        *(float4*)(cp)     = make_float4(o[0], o[1], o[2], o[3]);
        *(float4*)(cp + 4) = make_float4(o[4], o[5], o[6], o[7]);
    }
}

// =====================================================================
// Phase 2: recurrent scan (R7 structure + paired b64 egress).
// Grid (8,16), cluster (8,1,1). Cluster grp owns batch rows 4*grp..+3;
// CTA rank owns units [32*rank, +32). Lane (w, j4, ks): u = rank*32+w*4+j4,
// k-slice ks. Weights packed along k in regs (64 u64/thread).
// Per step: LDS.128 h-pairs + FFMA2 -> warp shuffle reduce-scatter ->
// owner lanes (ks<4 = row) activations (c in reg) -> paired st.async.b64
// broadcast (64 storer lanes x 8 dests, incl self) with mbarrier
// tx-completion. No __syncthreads / cluster.sync in the loop.
// =====================================================================
__global__ __launch_bounds__(256, 1) __cluster_dims__(8, 1, 1)
void lstm_scan(const float* __restrict__ Wh, float* __restrict__ out)
{
    __shared__ u64 hbuf[2][4][128];   // [parity][row][k-pair slot]
    __shared__ u64 mbar[2];

    const int tid  = threadIdx.x;
    const int w    = tid >> 5;
    const int lane = tid & 31;
    const int j4   = lane >> 3;          // unit-within-group
    const int ks   = lane & 7;           // k-slice / row id
    const int rank = blockIdx.x;
    const int grp  = blockIdx.y;
    const int u    = rank * 32 + w * 4 + j4;

    // --- weights packed along k: wp[g][m], k-pair kp = ks*16+m ---
    u64 wp[4][16];
#pragma unroll
    for (int m = 0; m < 16; m++) {
        const int kA = ks * 32 + 2 * m;
#pragma unroll
        for (int g = 0; g < 4; g++) {
            wp[g][m] = pk2(Wh[(size_t)kA * 1024 + g * 256 + u],
                           Wh[(size_t)(kA + 1) * 1024 + g * 256 + u]);
        }
    }

    // init: zero parity-0 buffer, init + arm both mbarriers
    {
        u64* hz = &hbuf[0][0][0];
        hz[tid] = 0ull; hz[tid + 256] = 0ull;
    }
    const u32 hb_l = smem_u32(&hbuf[0][0][0]);
    const u32 mb_l = smem_u32(&mbar[0]);
    if (tid == 0) {
        mbar_init(mb_l, 1);
        mbar_init(mb_l + 8, 1);
        mbar_expect(mb_l, 4096);       // buffer 0: fed at t=1, used t=2
        mbar_expect(mb_l + 8, 4096);   // buffer 1: fed at t=0, used t=1
    }
    __syncthreads();
    cluster_sync_();   // peers armed + hbuf[0] zeroed everywhere

    // owner-lane constants (ks<4 => row ks)
    const int rowg = grp * 4 + ks;
    const size_t xgBase  = ((size_t)rowg * T_SZ) * 1024 + u;
    const size_t outBase = ((size_t)rowg * T_SZ) * H_SZ + u;

    // producer slot for (row=ks, unit-pair of even u):
    const int kp  = u >> 1;
    const int mq  = kp & 15;
    const u32 off0 = (u32)(ks * 1024 + ((mq >> 1) * 16 + (kp >> 4) * 2 + (mq & 1)) * 8);
    const bool storer = (ks < 4) && ((j4 & 1) == 0);

    u32 hdst[8], mrem[8];
#pragma unroll
    for (int rk = 0; rk < 8; rk++) {
        hdst[rk] = mapa_sh(hb_l, (u32)rk) + off0;
        mrem[rk] = mapa_sh(mb_l, (u32)rk);
    }

    float c = 0.0f, h = 0.0f;
    u32 ph0 = 0, ph1 = 0;

#pragma unroll 1
    for (int t = 0; t < T_SZ; t++) {
        const int b = t & 1;

        // xg loads for this step (issued before any waiting)
        float xi = 0.f, xf = 0.f, xgg = 0.f, xo = 0.f;
        if (ks < 4) {
            const float* xp = g_xg + xgBase + (size_t)t * 1024;
            xi  = __ldg(xp);
            xf  = __ldg(xp + 256);
            xgg = __ldg(xp + 512);
            xo  = __ldg(xp + 768);
        }

        if (t > 0) {
            const u32 phb = b ? ph1 : ph0;
            mbar_wait(mb_l + (b << 3), phb);
            if (b) ph1 ^= 1; else ph0 ^= 1;
            if (tid == 0) mbar_expect(mb_l + (b << 3), 4096);  // re-arm for t+2
        }

        // ---- partial GEMM over this thread's 32-k slice ----
        u64 acc[4][4];
#pragma unroll
        for (int r = 0; r < 4; r++)
#pragma unroll
            for (int g = 0; g < 4; g++) acc[r][g] = 0ull;

        const u64* hbp = &hbuf[b][0][0];
#pragma unroll
        for (int m2 = 0; m2 < 8; m2++) {
#pragma unroll
            for (int r = 0; r < 4; r++) {
                ulonglong2 hv = *(const ulonglong2*)(hbp + r * 128 + m2 * 16 + ks * 2);
#pragma unroll
                for (int g = 0; g < 4; g++) {
                    acc[r][g] = fma2(hv.x, wp[g][2 * m2],     acc[r][g]);
                    acc[r][g] = fma2(hv.y, wp[g][2 * m2 + 1], acc[r][g]);
                }
            }
        }

        // ---- warp reduce-scatter over ks (lane ends with row ks&3) ----
        const bool pb = (ks & 1);
        const bool qb = (ks & 2);
        u64 kk[4];
#pragma unroll
        for (int g = 0; g < 4; g++) {
            u64 sA = pb ? acc[0][g] : acc[1][g];
            u64 sB = pb ? acc[2][g] : acc[3][g];
            u64 rA = __shfl_xor_sync(0xffffffffu, sA, 1);
            u64 rB = __shfl_xor_sync(0xffffffffu, sB, 1);
            u64 k0 = add2(pb ? acc[1][g] : acc[0][g], rA);
            u64 k1 = add2(pb ? acc[3][g] : acc[2][g], rB);
            u64 s2 = qb ? k0 : k1;
            u64 r2 = __shfl_xor_sync(0xffffffffu, s2, 2);
            u64 kx = add2(qb ? k1 : k0, r2);
            kk[g] = add2(kx, __shfl_xor_sync(0xffffffffu, kx, 4));
        }

        // ---- owners: activations ----
        if (ks < 4) {
            float e0, e1;
            unpk(kk[0], e0, e1); const float gi = e0 + e1 + xi;
            unpk(kk[1], e0, e1); const float gf = e0 + e1 + xf;
            unpk(kk[2], e0, e1); const float gg = e0 + e1 + xgg;
            unpk(kk[3], e0, e1); const float go = e0 + e1 + xo;

            c = sigm(gf) * c + sigm(gi) * tanh_(gg);
            h = sigm(go) * tanh_(c);
        }

        // ---- paired broadcast of h for step t+1 (critical path first) ----
        if (t < T_SZ - 1) {
            const float hpart = __shfl_xor_sync(0xffffffffu, h, 8);  // u+1's h
            if (storer) {
                const u64 val = pk2(h, hpart);
                const u32 po = (u32)((b ^ 1) << 12);    // parity stride 4096B
                const u32 mo = (u32)((b ^ 1) << 3);
#pragma unroll
                for (int rk = 0; rk < 8; rk++)
                    st_async_b64(hdst[rk] + po, val, mrem[rk] + mo);
            }
        }

        // ---- non-critical output store ----
        if (ks < 4)
            out[outBase + (size_t)t * H_SZ] = h;
    }

    // finals: h_T then c_T, each [B, H], appended after Hs
    if (ks < 4) {
        float* fin = out + (size_t)B_SZ * T_SZ * H_SZ;
        fin[(size_t)rowg * H_SZ + u] = h;
        fin[(size_t)B_SZ * H_SZ + (size_t)rowg * H_SZ + u] = c;
    }
}

extern "C" void kernel_launch(void* const* d_in, const int* in_sizes, int n_in,
                              void* d_out, int out_size) {
    const float* x    = (const float*)d_in[0];
    const float* W_i  = (const float*)d_in[1];
    const float* W_h  = (const float*)d_in[2];
    const float* bias = (const float*)d_in[3];
    float* out = (float*)d_out;

    dim3 g1(1024 / 128, (B_SZ * T_SZ) / 128);
    xw_gemm<<<g1, 256>>>(x, W_i, bias);

    dim3 g2(8, 16);
    lstm_scan<<<g2, 256>>>(W_h, out);
}

// round 10
// speedup vs baseline: 1.1072x; 1.1072x over previous
#include <cuda_runtime.h>
#include <cstdint>
#include <cstddef>

typedef unsigned long long u64;
typedef unsigned int u32;

#define B_SZ 64
#define T_SZ 2048
#define H_SZ 256
#define G4   1024   // 4*H

// scratch: natural layout [m][gate*256+u] (gemm output)
__device__ float g_xg[(size_t)B_SZ * T_SZ * G4];
// scratch: gate-interleaved layout [m][u*4+gate] (scan input)
__device__ float g_xgi[(size_t)B_SZ * T_SZ * G4];

// ---------------- f32x2 helpers ----------------
__device__ __forceinline__ u64 pk2(float lo, float hi) {
    u64 r; asm("mov.b64 %0, {%1, %2};" : "=l"(r) : "f"(lo), "f"(hi)); return r;
}
__device__ __forceinline__ u64 dup2(float a) {
    u64 r; asm("mov.b64 %0, {%1, %1};" : "=l"(r) : "f"(a)); return r;
}
__device__ __forceinline__ u64 fma2(u64 a, u64 b, u64 c) {
    u64 d; asm("fma.rn.f32x2 %0, %1, %2, %3;" : "=l"(d) : "l"(a), "l"(b), "l"(c)); return d;
}
__device__ __forceinline__ u64 add2(u64 a, u64 b) {
    u64 d; asm("add.rn.f32x2 %0, %1, %2;" : "=l"(d) : "l"(a), "l"(b)); return d;
}
__device__ __forceinline__ void unpk(u64 v, float& lo, float& hi) {
    asm("mov.b64 {%0, %1}, %2;" : "=f"(lo), "=f"(hi) : "l"(v));
}

// ---------------- cluster / mbarrier helpers ----------------
__device__ __forceinline__ u32 smem_u32(const void* p) {
    u32 a;
    asm("{ .reg .u64 t; cvta.to.shared.u64 t, %1; cvt.u32.u64 %0, t; }" : "=r"(a) : "l"(p));
    return a;
}
__device__ __forceinline__ u32 mapa_sh(u32 a, u32 rk) {
    u32 r; asm("mapa.shared::cluster.u32 %0, %1, %2;" : "=r"(r) : "r"(a), "r"(rk)); return r;
}
__device__ __forceinline__ void cluster_sync_() {
    asm volatile("barrier.cluster.arrive.aligned;" ::: "memory");
    asm volatile("barrier.cluster.wait.aligned;" ::: "memory");
}
__device__ __forceinline__ void mbar_init(u32 a, u32 cnt) {
    asm volatile("mbarrier.init.shared.b64 [%0], %1;" :: "r"(a), "r"(cnt) : "memory");
}
__device__ __forceinline__ void mbar_expect(u32 a, u32 bytes) {
    asm volatile("mbarrier.arrive.expect_tx.shared.b64 _, [%0], %1;" :: "r"(a), "r"(bytes) : "memory");
}
__device__ __forceinline__ void mbar_wait(u32 a, u32 ph) {
    asm volatile(
        "{\n\t.reg .pred P;\n\t"
        "MW%=:\n\t"
        "mbarrier.try_wait.parity.acquire.cta.shared::cta.b64 P, [%0], %1, 0x989680;\n\t"
        "@!P bra MW%=;\n\t}"
        :: "r"(a), "r"(ph) : "memory");
}
__device__ __forceinline__ void st_async_f32(u32 dst, float v, u32 mb) {
    asm volatile(
        "st.async.shared::cluster.mbarrier::complete_tx::bytes.b32 [%0], %1, [%2];"
        :: "r"(dst), "r"(__float_as_uint(v)), "r"(mb) : "memory");
}

// ---------------- activations (exact, MUFU-based) ----------------
__device__ __forceinline__ float sigm(float x) {
    return __fdividef(1.0f, 1.0f + __expf(-x));
}
__device__ __forceinline__ float tanh_(float x) {
    return 1.0f - __fdividef(2.0f, __expf(2.0f * x) + 1.0f);
}

// =====================================================================
// Phase 1: g_xg[m][1024] = x[m][256] @ W_i[256][1024] + bias
// 128x128 tile, 256 threads, 8x8 microtile, k-chunk 16,
// double-buffered smem with register prefetch (1 sync / iter).
// =====================================================================
__global__ __launch_bounds__(256, 2) void xw_gemm(
    const float* __restrict__ A,      // x    [131072, 256]
    const float* __restrict__ W,      // W_i  [256, 1024]
    const float* __restrict__ bias)   // [1024]
{
    __shared__ float As[2][16][132];
    __shared__ float Bs[2][16][132];

    const int tid = threadIdx.x;
    const int tx = tid & 15;
    const int ty = tid >> 4;
    const int mBase = blockIdx.y * 128;
    const int nBase = blockIdx.x * 128;

    const int arow0 = tid >> 2,         akq0 = tid & 3;
    const int arow1 = (tid + 256) >> 2, akq1 = (tid + 256) & 3;
    const int bk0   = tid >> 5,         bnq0 = tid & 31;
    const int bk1   = (tid + 256) >> 5, bnq1 = (tid + 256) & 31;

    u64 acc[8][4];
    {
        const float* bp = bias + nBase + tx * 8;
        u64 b0 = pk2(bp[0], bp[1]);
        u64 b1 = pk2(bp[2], bp[3]);
        u64 b2 = pk2(bp[4], bp[5]);
        u64 b3 = pk2(bp[6], bp[7]);
#pragma unroll
        for (int i = 0; i < 8; i++) { acc[i][0] = b0; acc[i][1] = b1; acc[i][2] = b2; acc[i][3] = b3; }
    }

    float4 a_r0, a_r1, b_r0, b_r1;
    a_r0 = *(const float4*)(A + (size_t)(mBase + arow0) * 256 + akq0 * 4);
    a_r1 = *(const float4*)(A + (size_t)(mBase + arow1) * 256 + akq1 * 4);
    b_r0 = *(const float4*)(W + (size_t)bk0 * 1024 + nBase + bnq0 * 4);
    b_r1 = *(const float4*)(W + (size_t)bk1 * 1024 + nBase + bnq1 * 4);
    As[0][akq0 * 4 + 0][arow0] = a_r0.x; As[0][akq0 * 4 + 1][arow0] = a_r0.y;
    As[0][akq0 * 4 + 2][arow0] = a_r0.z; As[0][akq0 * 4 + 3][arow0] = a_r0.w;
    As[0][akq1 * 4 + 0][arow1] = a_r1.x; As[0][akq1 * 4 + 1][arow1] = a_r1.y;
    As[0][akq1 * 4 + 2][arow1] = a_r1.z; As[0][akq1 * 4 + 3][arow1] = a_r1.w;
    *(float4*)&Bs[0][bk0][bnq0 * 4] = b_r0;
    *(float4*)&Bs[0][bk1][bnq1 * 4] = b_r1;
    __syncthreads();

    int p = 0;
#pragma unroll 1
    for (int kc = 0; kc < 16; kc++) {
        if (kc < 15) {
            const int kb = (kc + 1) * 16;
            a_r0 = *(const float4*)(A + (size_t)(mBase + arow0) * 256 + kb + akq0 * 4);
            a_r1 = *(const float4*)(A + (size_t)(mBase + arow1) * 256 + kb + akq1 * 4);
            b_r0 = *(const float4*)(W + (size_t)(kb + bk0) * 1024 + nBase + bnq0 * 4);
            b_r1 = *(const float4*)(W + (size_t)(kb + bk1) * 1024 + nBase + bnq1 * 4);
        }
#pragma unroll
        for (int k = 0; k < 16; k++) {
            float4 a0 = *(float4*)&As[p][k][ty * 8];
            float4 a1 = *(float4*)&As[p][k][ty * 8 + 4];
            float4 b0 = *(float4*)&Bs[p][k][tx * 8];
            float4 b1 = *(float4*)&Bs[p][k][tx * 8 + 4];
            u64 bb0 = pk2(b0.x, b0.y), bb1 = pk2(b0.z, b0.w);
            u64 bb2 = pk2(b1.x, b1.y), bb3 = pk2(b1.z, b1.w);
            float aa[8] = {a0.x, a0.y, a0.z, a0.w, a1.x, a1.y, a1.z, a1.w};
#pragma unroll
            for (int i = 0; i < 8; i++) {
                u64 ad = dup2(aa[i]);
                acc[i][0] = fma2(ad, bb0, acc[i][0]);
                acc[i][1] = fma2(ad, bb1, acc[i][1]);
                acc[i][2] = fma2(ad, bb2, acc[i][2]);
                acc[i][3] = fma2(ad, bb3, acc[i][3]);
            }
        }
        if (kc < 15) {
            const int pn = p ^ 1;
            As[pn][akq0 * 4 + 0][arow0] = a_r0.x; As[pn][akq0 * 4 + 1][arow0] = a_r0.y;
            As[pn][akq0 * 4 + 2][arow0] = a_r0.z; As[pn][akq0 * 4 + 3][arow0] = a_r0.w;
            As[pn][akq1 * 4 + 0][arow1] = a_r1.x; As[pn][akq1 * 4 + 1][arow1] = a_r1.y;
            As[pn][akq1 * 4 + 2][arow1] = a_r1.z; As[pn][akq1 * 4 + 3][arow1] = a_r1.w;
            *(float4*)&Bs[pn][bk0][bnq0 * 4] = b_r0;
            *(float4*)&Bs[pn][bk1][bnq1 * 4] = b_r1;
            __syncthreads();
            p = pn;
        }
    }

#pragma unroll
    for (int i = 0; i < 8; i++) {
        float o[8];
        unpk(acc[i][0], o[0], o[1]); unpk(acc[i][1], o[2], o[3]);
        unpk(acc[i][2], o[4], o[5]); unpk(acc[i][3], o[6], o[7]);
        float* cp = g_xg + (size_t)(mBase + ty * 8 + i) * 1024 + nBase + tx * 8;
        *(float4*)(cp)     = make_float4(o[0], o[1], o[2], o[3]);
        *(float4*)(cp + 4) = make_float4(o[4], o[5], o[6], o[7]);
    }
}

// =====================================================================
// Repack: [m][gate*256+u] -> [m][u*4+gate]. Coalesced both directions.
// =====================================================================
__global__ __launch_bounds__(256, 8) void repack()
{
    const size_t m = blockIdx.x;          // 0 .. 131071
    const int u = threadIdx.x;            // 0 .. 255
    const float* src = g_xg + m * 1024;
    float4 v;
    v.x = src[u];
    v.y = src[256 + u];
    v.z = src[512 + u];
    v.w = src[768 + u];
    *(float4*)(g_xgi + m * 1024 + (size_t)u * 4) = v;
}

// =====================================================================
// Phase 2: recurrent scan (exact R7 structure, proven 5.0ms).
// Grid (8,16), cluster (8,1,1). Cluster grp owns batch rows 4*grp..+3;
// CTA rank owns units [32*rank,+32). Lane (w, j4, ks): u = rank*32+w*4+j4,
// k-slice ks. Weights packed along k in regs (64 u64/thread).
// Per step: float4 xg load -> mbar wait -> LDS.128 + FFMA2 ->
// warp shuffle reduce-scatter -> owner lanes (ks<4 = row) activations
// (c in reg) -> out STG -> per-owner st.async.b32 broadcast to 8 CTAs
// with mbarrier tx-completion. No CTA-wide sync in the loop.
// =====================================================================
__global__ __launch_bounds__(256, 1) __cluster_dims__(8, 1, 1)
void lstm_scan(const float* __restrict__ Wh, float* __restrict__ out)
{
    __shared__ u64 hbuf[2][4][128];   // [parity][row][k-pair slot]
    __shared__ u64 mbar[2];

    const int tid  = threadIdx.x;
    const int w    = tid >> 5;
    const int lane = tid & 31;
    const int j4   = lane >> 3;          // unit-within-group
    const int ks   = lane & 7;           // k-slice / row id
    const int rank = blockIdx.x;
    const int grp  = blockIdx.y;
    const int u    = rank * 32 + w * 4 + j4;

    // --- weights packed along k: wp[g][m], k-pair kp = ks*16+m ---
    u64 wp[4][16];
#pragma unroll
    for (int m = 0; m < 16; m++) {
        const int kA = ks * 32 + 2 * m;
#pragma unroll
        for (int g = 0; g < 4; g++) {
            wp[g][m] = pk2(Wh[(size_t)kA * 1024 + g * 256 + u],
                           Wh[(size_t)(kA + 1) * 1024 + g * 256 + u]);
        }
    }

    // init: zero parity-0 buffer, init + arm both mbarriers
    {
        u64* hz = &hbuf[0][0][0];
        hz[tid] = 0ull; hz[tid + 256] = 0ull;
    }
    const u32 hb_l = smem_u32(&hbuf[0][0][0]);
    const u32 mb_l = smem_u32(&mbar[0]);
    if (tid == 0) {
        mbar_init(mb_l, 1);
        mbar_init(mb_l + 8, 1);
        mbar_expect(mb_l, 4096);       // buffer 0: fed at t=1, used t=2
        mbar_expect(mb_l + 8, 4096);   // buffer 1: fed at t=0, used t=1
    }
    __syncthreads();
    cluster_sync_();   // peers armed + hbuf[0] zeroed everywhere

    // owner-lane constants (ks<4 => row ks)
    const int rowg = grp * 4 + ks;
    const size_t xgBase  = ((size_t)rowg * T_SZ) * 1024 + (size_t)u * 4;
    const size_t outBase = ((size_t)rowg * T_SZ) * H_SZ + u;

    // producer slot for (row=ks, unit u):
    const int kp  = u >> 1;
    const int mq  = kp & 15;
    const u32 off0 = (u32)(ks * 1024 + ((mq >> 1) * 16 + (kp >> 4) * 2 + (mq & 1)) * 8 + (u & 1) * 4);

    u32 hdst[8], mrem[8];
#pragma unroll
    for (int rk = 0; rk < 8; rk++) {
        hdst[rk] = mapa_sh(hb_l, (u32)rk) + off0;
        mrem[rk] = mapa_sh(mb_l, (u32)rk);
    }

    float c = 0.0f, h = 0.0f;
    u32 ph0 = 0, ph1 = 0;

#pragma unroll 1
    for (int t = 0; t < T_SZ; t++) {
        const int b = t & 1;

        // xg prefetch for this step — single float4, issued before the wait
        float4 xq = make_float4(0.f, 0.f, 0.f, 0.f);
        if (ks < 4)
            xq = *(const float4*)(g_xgi + xgBase + (size_t)t * 1024);

        if (t > 0) {
            const u32 phb = b ? ph1 : ph0;
            mbar_wait(mb_l + (b << 3), phb);
            if (b) ph1 ^= 1; else ph0 ^= 1;
            if (tid == 0) mbar_expect(mb_l + (b << 3), 4096);  // re-arm for t+2
        }

        // ---- partial GEMM over this thread's 32-k slice ----
        u64 acc[4][4];
#pragma unroll
        for (int r = 0; r < 4; r++)
#pragma unroll
            for (int g = 0; g < 4; g++) acc[r][g] = 0ull;

        const u64* hbp = &hbuf[b][0][0];
#pragma unroll
        for (int m2 = 0; m2 < 8; m2++) {
#pragma unroll
            for (int r = 0; r < 4; r++) {
                ulonglong2 hv = *(const ulonglong2*)(hbp + r * 128 + m2 * 16 + ks * 2);
#pragma unroll
                for (int g = 0; g < 4; g++) {
                    acc[r][g] = fma2(hv.x, wp[g][2 * m2],     acc[r][g]);
                    acc[r][g] = fma2(hv.y, wp[g][2 * m2 + 1], acc[r][g]);
                }
            }
        }

        // ---- warp reduce-scatter over ks (lane ends with row ks&3) ----
        const bool pb = (ks & 1);
        const bool qb = (ks & 2);
        u64 kk[4];
#pragma unroll
        for (int g = 0; g < 4; g++) {
            u64 sA = pb ? acc[0][g] : acc[1][g];
            u64 sB = pb ? acc[2][g] : acc[3][g];
            u64 rA = __shfl_xor_sync(0xffffffffu, sA, 1);
            u64 rB = __shfl_xor_sync(0xffffffffu, sB, 1);
            u64 k0 = add2(pb ? acc[1][g] : acc[0][g], rA);
            u64 k1 = add2(pb ? acc[3][g] : acc[2][g], rB);
            u64 s2 = qb ? k0 : k1;
            u64 r2 = __shfl_xor_sync(0xffffffffu, s2, 2);
            u64 kx = add2(qb ? k1 : k0, r2);
            kk[g] = add2(kx, __shfl_xor_sync(0xffffffffu, kx, 4));
        }

        // ---- owners: activations + output + broadcast ----
        if (ks < 4) {
            float e0, e1;
            unpk(kk[0], e0, e1); const float gi = e0 + e1 + xq.x;
            unpk(kk[1], e0, e1); const float gf = e0 + e1 + xq.y;
            unpk(kk[2], e0, e1); const float gg = e0 + e1 + xq.z;
            unpk(kk[3], e0, e1); const float go = e0 + e1 + xq.w;

            c = sigm(gf) * c + sigm(gi) * tanh_(gg);
            h = sigm(go) * tanh_(c);

            out[outBase + (size_t)t * H_SZ] = h;

            if (t < T_SZ - 1) {
                const u32 po = (u32)((b ^ 1) << 12);    // parity stride 4096B
                const u32 mo = (u32)((b ^ 1) << 3);
#pragma unroll
                for (int rk = 0; rk < 8; rk++)
                    st_async_f32(hdst[rk] + po, h, mrem[rk] + mo);
            }
        }
    }

    // finals: h_T then c_T, each [B, H], appended after Hs
    if (ks < 4) {
        float* fin = out + (size_t)B_SZ * T_SZ * H_SZ;
        fin[(size_t)rowg * H_SZ + u] = h;
        fin[(size_t)B_SZ * H_SZ + (size_t)rowg * H_SZ + u] = c;
    }
}

extern "C" void kernel_launch(void* const* d_in, const int* in_sizes, int n_in,
                              void* d_out, int out_size) {
    const float* x    = (const float*)d_in[0];
    const float* W_i  = (const float*)d_in[1];
    const float* W_h  = (const float*)d_in[2];
    const float* bias = (const float*)d_in[3];
    float* out = (float*)d_out;

    // Phase 1: xg = x @ W_i + bias (natural layout)
    dim3 g1(1024 / 128, (B_SZ * T_SZ) / 128);
    xw_gemm<<<g1, 256>>>(x, W_i, bias);

    // Repack to gate-interleaved layout for the scan
    repack<<<B_SZ * T_SZ, 256>>>();

    // Phase 2: recurrent scan (16 clusters of 8 CTAs)
    dim3 g2(8, 16);
    lstm_scan<<<g2, 256>>>(W_h, out);
}